// round 2
// baseline (speedup 1.0000x reference)
#include <cuda_runtime.h>

#define T_LEN 1024
#define HID 64
#define SB 4            // batch streams per CTA (per direction)
#define NTHREADS 512
#define NROWS 256       // 4*HID gate rows per direction

// Packed dual-fp32 FMA (Blackwell sm_100+): d = a*b + c on two f32 lanes.
__device__ __forceinline__ unsigned long long ffma2(unsigned long long a,
                                                    unsigned long long b,
                                                    unsigned long long c) {
    unsigned long long d;
    asm("fma.rn.f32x2 %0, %1, %2, %3;" : "=l"(d) : "l"(a), "l"(b), "l"(c));
    return d;
}

__device__ __forceinline__ float fast_sigmoid(float x) {
    return __fdividef(1.0f, 1.0f + __expf(-x));
}
__device__ __forceinline__ float fast_tanh(float x) {
    // tanh(x) = 1 - 2/(exp(2x)+1); saturates gracefully at +-inf
    return fmaf(-2.0f, __fdividef(1.0f, __expf(2.0f * x) + 1.0f), 1.0f);
}

__global__ __launch_bounds__(NTHREADS, 1)
void bilstm_kernel(const float* __restrict__ x,
                   const float* __restrict__ Wih_f, const float* __restrict__ Whh_f,
                   const float* __restrict__ bih_f, const float* __restrict__ bhh_f,
                   const float* __restrict__ Wih_b, const float* __restrict__ Whh_b,
                   const float* __restrict__ bih_b, const float* __restrict__ bhh_b,
                   const float* __restrict__ fc_w, const float* __restrict__ fc_b,
                   float* __restrict__ out)
{
    __shared__ float xs[SB][T_LEN];        // staged inputs, 16 KB
    __shared__ float hsm[2][SB][HID];      // hidden state, [dir][stream][k]
    __shared__ float zsm[2][NROWS][5];     // gate preacts, padded stride 5 (bank-conflict free)
    __shared__ float ypart[2][SB][2];      // fc partial sums per half-warp

    const int tid  = threadIdx.x;
    const int d    = tid >> 8;        // 0 = forward, 1 = backward
    const int r    = tid & 255;       // gate row within direction
    const int k    = r & 63;          // hidden unit for gate phase
    const int s    = r >> 6;          // stream for gate phase
    const int lane = tid & 31;
    const int half = (r >> 5) & 1;

    const int b0 = blockIdx.x * SB;

    // Stage x for this CTA's 4 batch rows (coalesced).
    for (int idx = tid; idx < SB * T_LEN; idx += NTHREADS) {
        int ss = idx >> 10, tt = idx & (T_LEN - 1);
        xs[ss][tt] = x[(b0 + ss) * T_LEN + tt];
    }
    // Zero hidden state (exactly 512 floats = NTHREADS).
    ((float*)hsm)[tid] = 0.0f;

    const float* Whh = d ? Whh_b : Whh_f;
    const float* Wih = d ? Wih_b : Wih_f;
    const float* bih = d ? bih_b : bih_f;
    const float* bhh = d ? bhh_b : bhh_f;

    // Whh row for this thread, pre-packed as 32 f32x2 pairs (paired along K).
    unsigned long long wk[32];
    const unsigned long long* wrow = (const unsigned long long*)(Whh + r * HID);
    #pragma unroll
    for (int i = 0; i < 32; ++i) wk[i] = __ldg(wrow + i);

    const float wih  = Wih[r];
    const float base = bih[r] + bhh[r];
    const float fcw  = fc_w[d * HID + k];
    const float fcb  = fc_b[0];

    float c = 0.0f;  // cell state for (d, s, k), lives in a register forever

    __syncthreads();

    for (int t = 0; t < T_LEN; ++t) {
        // ---- matvec phase: thread computes z_r for all 4 streams ----
        const int xt = d ? (T_LEN - 1 - t) : t;
        float xv[SB];
        #pragma unroll
        for (int ss = 0; ss < SB; ++ss) xv[ss] = xs[ss][xt];

        unsigned long long acc[SB];
        #pragma unroll
        for (int ss = 0; ss < SB; ++ss) acc[ss] = 0ULL;

        #pragma unroll
        for (int i2 = 0; i2 < 16; ++i2) {
            #pragma unroll
            for (int ss = 0; ss < SB; ++ss) {
                // broadcast LDS.128: uniform address within each warp
                ulonglong2 hv = ((const ulonglong2*)&hsm[d][ss][0])[i2];
                acc[ss] = ffma2(hv.x, wk[2 * i2],     acc[ss]);
                acc[ss] = ffma2(hv.y, wk[2 * i2 + 1], acc[ss]);
            }
        }

        #pragma unroll
        for (int ss = 0; ss < SB; ++ss) {
            union { unsigned long long u; float2 f; } a;
            a.u = acc[ss];
            zsm[d][r][ss] = a.f.x + a.f.y + fmaf(xv[ss], wih, base);
        }
        __syncthreads();

        // ---- gate phase: thread owns hidden unit (d, s, k) ----
        const float zi = zsm[d][k      ][s];
        const float zf = zsm[d][64  + k][s];
        const float zg = zsm[d][128 + k][s];
        const float zo = zsm[d][192 + k][s];

        const float ig = fast_sigmoid(zi);
        const float fg = fast_sigmoid(zf);
        const float gg = fast_tanh(zg);
        const float og = fast_sigmoid(zo);
        c = fmaf(fg, c, ig * gg);
        const float hn = og * fast_tanh(c);
        hsm[d][s][k] = hn;

        // fc contribution: reduce fcw*hn over the 64 threads of (d, s)
        float p = fcw * hn;
        #pragma unroll
        for (int off = 16; off; off >>= 1)
            p += __shfl_xor_sync(0xffffffffu, p, off);
        if (lane == 0) ypart[d][s][half] = p;
        __syncthreads();

        if (tid < SB) {
            float y = ypart[0][tid][0] + ypart[0][tid][1]
                    + ypart[1][tid][0] + ypart[1][tid][1] + fcb;
            out[(b0 + tid) * T_LEN + t] = y;
        }
    }
}

extern "C" void kernel_launch(void* const* d_in, const int* in_sizes, int n_in,
                              void* d_out, int out_size) {
    const float* x     = (const float*)d_in[0];
    const float* Wih_f = (const float*)d_in[1];
    const float* Whh_f = (const float*)d_in[2];
    const float* bih_f = (const float*)d_in[3];
    const float* bhh_f = (const float*)d_in[4];
    const float* Wih_b = (const float*)d_in[5];
    const float* Whh_b = (const float*)d_in[6];
    const float* bih_b = (const float*)d_in[7];
    const float* bhh_b = (const float*)d_in[8];
    const float* fc_w  = (const float*)d_in[9];
    const float* fc_b  = (const float*)d_in[10];
    float* out = (float*)d_out;

    const int B = in_sizes[0] / T_LEN;   // 1024
    const int grid = B / SB;             // 256 CTAs

    bilstm_kernel<<<grid, NTHREADS>>>(x, Wih_f, Whh_f, bih_f, bhh_f,
                                      Wih_b, Whh_b, bih_b, bhh_b,
                                      fc_w, fc_b, out);
    (void)n_in; (void)out_size;
}

// round 3
// speedup vs baseline: 1.1866x; 1.1866x over previous
#include <cuda_runtime.h>

#define T_LEN 1024
#define HID   64
#define SB    8          // batch streams per CTA (both directions computed in-CTA)
#define NTH   256        // 256 threads: tid>>7 = dir, tid&127 = row-pair index

// Packed dual-fp32 FMA (Blackwell sm_100+): two f32 MACs per instruction.
__device__ __forceinline__ unsigned long long ffma2(unsigned long long a,
                                                    unsigned long long b,
                                                    unsigned long long c) {
    unsigned long long d;
    asm("fma.rn.f32x2 %0, %1, %2, %3;" : "=l"(d) : "l"(a), "l"(b), "l"(c));
    return d;
}

__device__ __forceinline__ float fast_sigmoid(float x) {
    return __fdividef(1.0f, 1.0f + __expf(-x));
}
__device__ __forceinline__ float fast_tanh(float x) {
    return fmaf(-2.0f, __fdividef(1.0f, __expf(2.0f * x) + 1.0f), 1.0f);
}

__global__ __launch_bounds__(NTH, 1)
void bilstm_kernel(const float* __restrict__ x,
                   const float* __restrict__ Wih_f, const float* __restrict__ Whh_f,
                   const float* __restrict__ bih_f, const float* __restrict__ bhh_f,
                   const float* __restrict__ Wih_b, const float* __restrict__ Whh_b,
                   const float* __restrict__ bih_b, const float* __restrict__ bhh_b,
                   const float* __restrict__ fc_w, const float* __restrict__ fc_b,
                   float* __restrict__ out)
{
    __shared__ __align__(16) float xs[SB][T_LEN];      // 32 KB staged input
    __shared__ __align__(16) float hsm[2][SB][HID];    // hidden state  [dir][s][k]
    __shared__ float abuf[2][HID][9];                  // sig(i)*tanh(g), pad 9 (bank-free)

    const int tid  = threadIdx.x;
    const int d    = tid >> 7;          // direction
    const int kq   = tid & 127;         // row-pair index: rows (kq, kq+128) of dir d
    const int lane = tid & 31;
    const int b0   = blockIdx.x * SB;

    // ---- stage x (coalesced) + zero h ----
    for (int idx = tid; idx < SB * T_LEN; idx += NTH) {
        int ss = idx >> 10, tt = idx & (T_LEN - 1);
        xs[ss][tt] = x[(b0 + ss) * T_LEN + tt];
    }
    for (int idx = tid; idx < 2 * SB * HID; idx += NTH)
        ((float*)hsm)[idx] = 0.0f;

    const float* Whh = d ? Whh_b : Whh_f;
    const float* Wih = d ? Wih_b : Wih_f;
    const float* bih = d ? bih_b : bih_f;
    const float* bhh = d ? bhh_b : bhh_f;

    const int rA = kq;          // row A:   i-gate (kq<64, k=kq)   or f-gate (kq>=64, k=kq-64)
    const int rB = kq + 128;    // row B:   g-gate                  or o-gate

    // Whh rows pre-packed as f32x2 pairs in registers: 128 regs of weights.
    unsigned long long wkA[32], wkB[32];
    {
        const unsigned long long* wa = (const unsigned long long*)(Whh + rA * HID);
        const unsigned long long* wb = (const unsigned long long*)(Whh + rB * HID);
        #pragma unroll
        for (int i = 0; i < 32; ++i) { wkA[i] = __ldg(wa + i); wkB[i] = __ldg(wb + i); }
    }
    const float wihA = Wih[rA], wihB = Wih[rB];
    const float baseA = bih[rA] + bhh[rA];
    const float baseB = bih[rB] + bhh[rB];

    const bool isA = (kq < 64);         // owns (i,g); else owns (f,o)
    const int  k   = isA ? kq : (kq - 64);
    const float fcb = fc_b[0];

    // fc weights for the output phase: warp w handles stream w, lane handles 4 elems.
    const float4 fcw4 = *(const float4*)(fc_w + lane * 4);
    const int s_out = tid >> 5;

    float c[SB];                        // cell state (only meaningful in f/o threads)
    #pragma unroll
    for (int ss = 0; ss < SB; ++ss) c[ss] = 0.0f;

    __syncthreads();

    for (int t = 0; t < T_LEN; ++t) {
        // ================= matvec: z = Whh @ h (+ Wih x + b) ==================
        const int xt = d ? (T_LEN - 1 - t) : t;

        unsigned long long accA[SB], accB[SB];
        #pragma unroll
        for (int ss = 0; ss < SB; ++ss) { accA[ss] = 0ULL; accB[ss] = 0ULL; }

        #pragma unroll
        for (int i2 = 0; i2 < 16; ++i2) {
            const unsigned long long wA0 = wkA[2 * i2], wA1 = wkA[2 * i2 + 1];
            const unsigned long long wB0 = wkB[2 * i2], wB1 = wkB[2 * i2 + 1];
            #pragma unroll
            for (int ss = 0; ss < SB; ++ss) {
                // broadcast LDS.128 (warp-uniform address), reused by BOTH rows
                ulonglong2 hv = ((const ulonglong2*)&hsm[d][ss][0])[i2];
                accA[ss] = ffma2(hv.x, wA0, accA[ss]);
                accA[ss] = ffma2(hv.y, wA1, accA[ss]);
                accB[ss] = ffma2(hv.x, wB0, accB[ss]);
                accB[ss] = ffma2(hv.y, wB1, accB[ss]);
            }
        }

        float zA[SB], zB[SB];
        #pragma unroll
        for (int ss = 0; ss < SB; ++ss) {
            const float xv = xs[ss][xt];
            union { unsigned long long u; float2 f; } a, b;
            a.u = accA[ss]; b.u = accB[ss];
            zA[ss] = a.f.x + a.f.y + fmaf(xv, wihA, baseA);
            zB[ss] = b.f.x + b.f.y + fmaf(xv, wihB, baseB);
        }

        // ================= gate phase =================
        float fg[SB], og[SB];
        if (isA) {
            // this thread holds z_i (A) and z_g (B): publish sig(i)*tanh(g)
            #pragma unroll
            for (int ss = 0; ss < SB; ++ss)
                abuf[d][k][ss] = fast_sigmoid(zA[ss]) * fast_tanh(zB[ss]);
        } else {
            // this thread holds z_f (A) and z_o (B)
            #pragma unroll
            for (int ss = 0; ss < SB; ++ss) {
                fg[ss] = fast_sigmoid(zA[ss]);
                og[ss] = fast_sigmoid(zB[ss]);
            }
        }
        __syncthreads();

        if (!isA) {
            #pragma unroll
            for (int ss = 0; ss < SB; ++ss) {
                c[ss] = fmaf(fg[ss], c[ss], abuf[d][k][ss]);
                hsm[d][ss][k] = og[ss] * fast_tanh(c[ss]);
            }
        }
        __syncthreads();

        // ================= output: out[s,t] = fc_w . [hf;hb] + fc_b ============
        {
            const int m = lane * 4;                         // element index in [0,128)
            const float4 hv4 = *(const float4*)&hsm[m >> 6][s_out][m & 63];
            float p = fcw4.x * hv4.x + fcw4.y * hv4.y + fcw4.z * hv4.z + fcw4.w * hv4.w;
            #pragma unroll
            for (int off = 16; off; off >>= 1)
                p += __shfl_xor_sync(0xffffffffu, p, off);
            if (lane == 0)
                out[(b0 + s_out) * T_LEN + t] = p + fcb;
        }
        // hsm is not rewritten until after the next iteration's __syncthreads(),
        // so no extra barrier is needed here.
    }
}

extern "C" void kernel_launch(void* const* d_in, const int* in_sizes, int n_in,
                              void* d_out, int out_size) {
    const float* x     = (const float*)d_in[0];
    const float* Wih_f = (const float*)d_in[1];
    const float* Whh_f = (const float*)d_in[2];
    const float* bih_f = (const float*)d_in[3];
    const float* bhh_f = (const float*)d_in[4];
    const float* Wih_b = (const float*)d_in[5];
    const float* Whh_b = (const float*)d_in[6];
    const float* bih_b = (const float*)d_in[7];
    const float* bhh_b = (const float*)d_in[8];
    const float* fc_w  = (const float*)d_in[9];
    const float* fc_b  = (const float*)d_in[10];
    float* out = (float*)d_out;

    const int B = in_sizes[0] / T_LEN;   // 1024
    const int grid = B / SB;             // 128 CTAs -> single wave on 148 SMs

    bilstm_kernel<<<grid, NTH>>>(x, Wih_f, Whh_f, bih_f, bhh_f,
                                 Wih_b, Whh_b, bih_b, bhh_b,
                                 fc_w, fc_b, out);
    (void)n_in; (void)out_size;
}